// round 3
// baseline (speedup 1.0000x reference)
#include <cuda_runtime.h>

#define NUM_EDGES   500000
#define SIZE1       80000
#define SIZE2       80000
#define BATCH       8

// Batch-minor scratch: xt[s*8 + b], out_t[s*8 + b]. 2.56 MB each, L2-resident.
__device__ float g_xt[SIZE1 * BATCH];
__device__ float g_out_t[SIZE2 * BATCH];

// ---------------------------------------------------------------------------
// Prep kernel (one thread per node index s, SIZE1 == SIZE2 == 80000):
//  1. transpose x[b, s] -> xt[s, b]   (loads coalesced per fixed b; stores
//     2 consecutive float4 per thread -> fully coalesced 32B/thread)
//  2. init out_t[s, b] = bias[s] = eps_b[s]*exp(b_log_var[s]) + b_mean[s]
// ---------------------------------------------------------------------------
__global__ void __launch_bounds__(256)
prep_kernel(const float* __restrict__ x,
            const float* __restrict__ b_mean,
            const float* __restrict__ b_log_var,
            const float* __restrict__ eps_b) {
    int s = blockIdx.x * blockDim.x + threadIdx.x;
    if (s >= SIZE1) return;

    float4 lo, hi;
    lo.x = __ldg(&x[0 * SIZE1 + s]);
    lo.y = __ldg(&x[1 * SIZE1 + s]);
    lo.z = __ldg(&x[2 * SIZE1 + s]);
    lo.w = __ldg(&x[3 * SIZE1 + s]);
    hi.x = __ldg(&x[4 * SIZE1 + s]);
    hi.y = __ldg(&x[5 * SIZE1 + s]);
    hi.z = __ldg(&x[6 * SIZE1 + s]);
    hi.w = __ldg(&x[7 * SIZE1 + s]);
    float4* xt4 = reinterpret_cast<float4*>(g_xt + (size_t)s * 8);
    xt4[0] = lo;
    xt4[1] = hi;

    float bias = fmaf(__ldg(&eps_b[s]), __expf(__ldg(&b_log_var[s])), __ldg(&b_mean[s]));
    float4 bv = make_float4(bias, bias, bias, bias);
    float4* ot4 = reinterpret_cast<float4*>(g_out_t + (size_t)s * 8);
    ot4[0] = bv;
    ot4[1] = bv;
}

// ---------------------------------------------------------------------------
// Edge kernel: one thread per graph edge. Dense 4x4 weight block per edge
// (flat index e*16 + i*4 + j):
//   out_t[dst*4 + j][b] += sum_i val[i][j] * xt[src*4 + i][b]
// xt rows src4..src4+3 = one contiguous 128B-aligned 128B block (full sectors).
// Output: 8 red.v4 covering one contiguous 128B-aligned block at dst*128.
// ---------------------------------------------------------------------------
__global__ void __launch_bounds__(256)
spmm_edge_kernel(const float4* __restrict__ w_mean4,
                 const float4* __restrict__ w_lv4,
                 const float4* __restrict__ eps_w4,
                 const int* __restrict__ rows,
                 const int* __restrict__ cols) {
    int e = blockIdx.x * blockDim.x + threadIdx.x;
    if (e >= NUM_EDGES) return;

    const int base = e * 4;  // float4 index into the 16-float block

    // v[i] = vals for fixed i across j (float4 over j)
    float4 v[4];
#pragma unroll
    for (int i = 0; i < 4; i++) {
        float4 m  = __ldg(&w_mean4[base + i]);
        float4 lv = __ldg(&w_lv4[base + i]);
        float4 ep = __ldg(&eps_w4[base + i]);
        v[i].x = fmaf(ep.x, __expf(lv.x), m.x);
        v[i].y = fmaf(ep.y, __expf(lv.y), m.y);
        v[i].z = fmaf(ep.z, __expf(lv.z), m.z);
        v[i].w = fmaf(ep.w, __expf(lv.w), m.w);
    }

    const int dst4 = __ldg(&rows[e * 16]);   // dst*4
    const int src4 = __ldg(&cols[e * 16]);   // src*4

    // xt[src4 + i][b] : 4 rows x 32B, contiguous 128B block
    float4 xa[4][2];
    const float4* xp = reinterpret_cast<const float4*>(g_xt + (size_t)src4 * 8);
#pragma unroll
    for (int i = 0; i < 4; i++) {
        xa[i][0] = __ldg(&xp[i * 2 + 0]);   // b = 0..3
        xa[i][1] = __ldg(&xp[i * 2 + 1]);   // b = 4..7
    }

    float* obase = g_out_t + (size_t)dst4 * 8;
#pragma unroll
    for (int j = 0; j < 4; j++) {
        // vj[i] = v[i] component j
        float vj0 = (j == 0) ? v[0].x : (j == 1) ? v[0].y : (j == 2) ? v[0].z : v[0].w;
        float vj1 = (j == 0) ? v[1].x : (j == 1) ? v[1].y : (j == 2) ? v[1].z : v[1].w;
        float vj2 = (j == 0) ? v[2].x : (j == 1) ? v[2].y : (j == 2) ? v[2].z : v[2].w;
        float vj3 = (j == 0) ? v[3].x : (j == 1) ? v[3].y : (j == 2) ? v[3].z : v[3].w;

        float4 alo, ahi;
        alo.x = vj0 * xa[0][0].x; alo.y = vj0 * xa[0][0].y;
        alo.z = vj0 * xa[0][0].z; alo.w = vj0 * xa[0][0].w;
        ahi.x = vj0 * xa[0][1].x; ahi.y = vj0 * xa[0][1].y;
        ahi.z = vj0 * xa[0][1].z; ahi.w = vj0 * xa[0][1].w;

        alo.x = fmaf(vj1, xa[1][0].x, alo.x); alo.y = fmaf(vj1, xa[1][0].y, alo.y);
        alo.z = fmaf(vj1, xa[1][0].z, alo.z); alo.w = fmaf(vj1, xa[1][0].w, alo.w);
        ahi.x = fmaf(vj1, xa[1][1].x, ahi.x); ahi.y = fmaf(vj1, xa[1][1].y, ahi.y);
        ahi.z = fmaf(vj1, xa[1][1].z, ahi.z); ahi.w = fmaf(vj1, xa[1][1].w, ahi.w);

        alo.x = fmaf(vj2, xa[2][0].x, alo.x); alo.y = fmaf(vj2, xa[2][0].y, alo.y);
        alo.z = fmaf(vj2, xa[2][0].z, alo.z); alo.w = fmaf(vj2, xa[2][0].w, alo.w);
        ahi.x = fmaf(vj2, xa[2][1].x, ahi.x); ahi.y = fmaf(vj2, xa[2][1].y, ahi.y);
        ahi.z = fmaf(vj2, xa[2][1].z, ahi.z); ahi.w = fmaf(vj2, xa[2][1].w, ahi.w);

        alo.x = fmaf(vj3, xa[3][0].x, alo.x); alo.y = fmaf(vj3, xa[3][0].y, alo.y);
        alo.z = fmaf(vj3, xa[3][0].z, alo.z); alo.w = fmaf(vj3, xa[3][0].w, alo.w);
        ahi.x = fmaf(vj3, xa[3][1].x, ahi.x); ahi.y = fmaf(vj3, xa[3][1].y, ahi.y);
        ahi.z = fmaf(vj3, xa[3][1].z, ahi.z); ahi.w = fmaf(vj3, xa[3][1].w, ahi.w);

        float* oaddr = obase + (size_t)j * 8;
        asm volatile("red.global.add.v4.f32 [%0], {%1, %2, %3, %4};"
                     :: "l"(oaddr), "f"(alo.x), "f"(alo.y), "f"(alo.z), "f"(alo.w)
                     : "memory");
        asm volatile("red.global.add.v4.f32 [%0], {%1, %2, %3, %4};"
                     :: "l"(oaddr + 4), "f"(ahi.x), "f"(ahi.y), "f"(ahi.z), "f"(ahi.w)
                     : "memory");
    }
}

// ---------------------------------------------------------------------------
// Finalize: out[b*SIZE2 + s] = out_t[s*8 + b]; zero the kl tail.
// Writes coalesced; reads are strided but out_t is L2-resident.
// ---------------------------------------------------------------------------
__global__ void __launch_bounds__(256)
finalize_kernel(float* __restrict__ out, int out_size) {
    int idx = blockIdx.x * blockDim.x + threadIdx.x;
    const int total = BATCH * SIZE2;
    if (idx < total) {
        int b = idx / SIZE2;
        int s = idx - b * SIZE2;
        out[idx] = g_out_t[(size_t)s * 8 + b];
    } else if (idx < out_size) {
        out[idx] = 0.0f;  // kl = 0
    }
}

extern "C" void kernel_launch(void* const* d_in, const int* in_sizes, int n_in,
                              void* d_out, int out_size) {
    const float* x      = (const float*)d_in[0];
    const float* w_mean = (const float*)d_in[1];
    const float* w_lv   = (const float*)d_in[2];
    const float* b_mean = (const float*)d_in[3];
    const float* b_lv   = (const float*)d_in[4];
    const float* eps_w  = (const float*)d_in[5];
    const float* eps_b  = (const float*)d_in[6];
    const int*   rows   = (const int*)d_in[7];
    const int*   cols   = (const int*)d_in[8];
    float* out = (float*)d_out;

    prep_kernel<<<(SIZE1 + 255) / 256, 256>>>(x, b_mean, b_lv, eps_b);

    spmm_edge_kernel<<<(NUM_EDGES + 255) / 256, 256>>>(
        (const float4*)w_mean, (const float4*)w_lv, (const float4*)eps_w,
        rows, cols);

    finalize_kernel<<<(out_size + 255) / 256, 256>>>(out, out_size);
}

// round 5
// speedup vs baseline: 1.0899x; 1.0899x over previous
#include <cuda_runtime.h>

#define NUM_EDGES   500000
#define SIZE1       80000
#define SIZE2       80000
#define BATCH       8

// Batch-minor copy of x: xt[s*8 + b]. 2.56 MB, L2-resident during edge kernel.
__device__ float g_xt[SIZE1 * BATCH];

// ---------------------------------------------------------------------------
// Transpose x[b, s] -> xt[s, b]. One thread per node s.
// Loads coalesced per plane; stores 32B contiguous per thread.
// ---------------------------------------------------------------------------
__global__ void __launch_bounds__(256)
transpose_x_kernel(const float* __restrict__ x) {
    int s = blockIdx.x * blockDim.x + threadIdx.x;
    if (s >= SIZE1) return;

    float4 lo, hi;
    lo.x = __ldg(&x[0 * SIZE1 + s]);
    lo.y = __ldg(&x[1 * SIZE1 + s]);
    lo.z = __ldg(&x[2 * SIZE1 + s]);
    lo.w = __ldg(&x[3 * SIZE1 + s]);
    hi.x = __ldg(&x[4 * SIZE1 + s]);
    hi.y = __ldg(&x[5 * SIZE1 + s]);
    hi.z = __ldg(&x[6 * SIZE1 + s]);
    hi.w = __ldg(&x[7 * SIZE1 + s]);
    float4* xt4 = reinterpret_cast<float4*>(g_xt + (size_t)s * 8);
    xt4[0] = lo;
    xt4[1] = hi;
}

// ---------------------------------------------------------------------------
// Init out (batch-major) with reparameterized bias; zero the kl tail.
// ---------------------------------------------------------------------------
__global__ void __launch_bounds__(256)
init_out_kernel(float* __restrict__ out,
                const float* __restrict__ b_mean,
                const float* __restrict__ b_log_var,
                const float* __restrict__ eps_b,
                int out_size) {
    int idx = blockIdx.x * blockDim.x + threadIdx.x;
    const int total = BATCH * SIZE2;
    if (idx < total) {
        int r = idx % SIZE2;
        out[idx] = fmaf(__ldg(&eps_b[r]), __expf(__ldg(&b_log_var[r])), __ldg(&b_mean[r]));
    } else if (idx < out_size) {
        out[idx] = 0.0f;   // kl = 0
    }
}

__device__ __forceinline__ float comp(const float4& f, int c) {
    return (c == 0) ? f.x : (c == 1) ? f.y : (c == 2) ? f.z : f.w;
}

// ---------------------------------------------------------------------------
// Edge kernel: one thread per graph edge. Dense 4x4 weight block per edge.
//   out[b, dst*4 + j] += sum_i val[i][j] * x[b, src*4 + i]
// x read from batch-minor xt: one contiguous 128B-aligned 128B block/edge.
// Output: batch-major scattered red.v4 (verified-fast layout: 8 addresses in
// 8 different batch planes -> parallel L2 atomic ALUs).
// ---------------------------------------------------------------------------
__global__ void __launch_bounds__(256)
spmm_edge_kernel(const float4* __restrict__ w_mean4,
                 const float4* __restrict__ w_lv4,
                 const float4* __restrict__ eps_w4,
                 const int* __restrict__ rows,
                 const int* __restrict__ cols,
                 float* __restrict__ out) {
    int e = blockIdx.x * blockDim.x + threadIdx.x;
    if (e >= NUM_EDGES) return;

    const int base = e * 4;  // float4 index into the 16-float block

    // v[i] = vals for fixed i across j (float4 over j)
    float4 v[4];
#pragma unroll
    for (int i = 0; i < 4; i++) {
        float4 m  = __ldg(&w_mean4[base + i]);
        float4 lv = __ldg(&w_lv4[base + i]);
        float4 ep = __ldg(&eps_w4[base + i]);
        v[i].x = fmaf(ep.x, __expf(lv.x), m.x);
        v[i].y = fmaf(ep.y, __expf(lv.y), m.y);
        v[i].z = fmaf(ep.z, __expf(lv.z), m.z);
        v[i].w = fmaf(ep.w, __expf(lv.w), m.w);
    }

    const int dst4 = __ldg(&rows[e * 16]);   // dst*4
    const int src4 = __ldg(&cols[e * 16]);   // src*4

    // xt[(src4+i)*8 + b] : contiguous 128B block (full sectors)
    float4 xa[4][2];
    const float4* xp = reinterpret_cast<const float4*>(g_xt + (size_t)src4 * 8);
#pragma unroll
    for (int i = 0; i < 4; i++) {
        xa[i][0] = __ldg(&xp[i * 2 + 0]);   // b = 0..3
        xa[i][1] = __ldg(&xp[i * 2 + 1]);   // b = 4..7
    }

#pragma unroll
    for (int b = 0; b < BATCH; b++) {
        const int half = b >> 2;
        const int c = b & 3;
        float x0 = comp(xa[0][half], c);
        float x1 = comp(xa[1][half], c);
        float x2 = comp(xa[2][half], c);
        float x3 = comp(xa[3][half], c);

        float4 acc;
        acc.x = x0 * v[0].x;
        acc.y = x0 * v[0].y;
        acc.z = x0 * v[0].z;
        acc.w = x0 * v[0].w;
        acc.x = fmaf(x1, v[1].x, acc.x);
        acc.y = fmaf(x1, v[1].y, acc.y);
        acc.z = fmaf(x1, v[1].z, acc.z);
        acc.w = fmaf(x1, v[1].w, acc.w);
        acc.x = fmaf(x2, v[2].x, acc.x);
        acc.y = fmaf(x2, v[2].y, acc.y);
        acc.z = fmaf(x2, v[2].z, acc.z);
        acc.w = fmaf(x2, v[2].w, acc.w);
        acc.x = fmaf(x3, v[3].x, acc.x);
        acc.y = fmaf(x3, v[3].y, acc.y);
        acc.z = fmaf(x3, v[3].z, acc.z);
        acc.w = fmaf(x3, v[3].w, acc.w);

        float* oaddr = out + (size_t)b * SIZE2 + dst4;
        asm volatile("red.global.add.v4.f32 [%0], {%1, %2, %3, %4};"
                     :: "l"(oaddr), "f"(acc.x), "f"(acc.y), "f"(acc.z), "f"(acc.w)
                     : "memory");
    }
}

extern "C" void kernel_launch(void* const* d_in, const int* in_sizes, int n_in,
                              void* d_out, int out_size) {
    const float* x      = (const float*)d_in[0];
    const float* w_mean = (const float*)d_in[1];
    const float* w_lv   = (const float*)d_in[2];
    const float* b_mean = (const float*)d_in[3];
    const float* b_lv   = (const float*)d_in[4];
    const float* eps_w  = (const float*)d_in[5];
    const float* eps_b  = (const float*)d_in[6];
    const int*   rows   = (const int*)d_in[7];
    const int*   cols   = (const int*)d_in[8];
    float* out = (float*)d_out;

    transpose_x_kernel<<<(SIZE1 + 255) / 256, 256>>>(x);

    init_out_kernel<<<(out_size + 255) / 256, 256>>>(out, b_mean, b_lv, eps_b, out_size);

    spmm_edge_kernel<<<(NUM_EDGES + 255) / 256, 256>>>(
        (const float4*)w_mean, (const float4*)w_lv, (const float4*)eps_w,
        rows, cols, out);
}

// round 7
// speedup vs baseline: 1.1743x; 1.0774x over previous
#include <cuda_runtime.h>

#define NUM_EDGES   500000
#define GS2         20000
#define SIZE1       80000
#define SIZE2       80000
#define BATCH       8
#define CAP         128          // bucket capacity per dst node (max degree ~50)

// Batch-minor copy of x: xt[s*8 + b]. 2.56 MB.
__device__ float g_xt[SIZE1 * BATCH];
// Per-dst edge count and fixed-capacity buckets of (eid, src4).
__device__ int  g_count[GS2];
__device__ int2 g_bucket[GS2 * CAP];   // 20.5 MB

// ---------------------------------------------------------------------------
// K1: transpose x[b,s] -> xt[s,b]; zero counters; zero kl tail of out.
// ---------------------------------------------------------------------------
__global__ void __launch_bounds__(256)
prep_kernel(const float* __restrict__ x, float* __restrict__ out, int out_size) {
    int s = blockIdx.x * blockDim.x + threadIdx.x;
    if (s >= SIZE1) return;

    float4 lo, hi;
    lo.x = __ldg(&x[0 * SIZE1 + s]);
    lo.y = __ldg(&x[1 * SIZE1 + s]);
    lo.z = __ldg(&x[2 * SIZE1 + s]);
    lo.w = __ldg(&x[3 * SIZE1 + s]);
    hi.x = __ldg(&x[4 * SIZE1 + s]);
    hi.y = __ldg(&x[5 * SIZE1 + s]);
    hi.z = __ldg(&x[6 * SIZE1 + s]);
    hi.w = __ldg(&x[7 * SIZE1 + s]);
    float4* xt4 = reinterpret_cast<float4*>(g_xt + (size_t)s * 8);
    xt4[0] = lo;
    xt4[1] = hi;

    if (s < GS2) g_count[s] = 0;
    if (s == 0) {
        for (int k = BATCH * SIZE2; k < out_size; k++) out[k] = 0.0f;  // kl = 0
    }
}

// ---------------------------------------------------------------------------
// K2: bin edges by destination node. One thread per edge.
// rows[e*16] == dst*4, cols[e*16] == src*4 (structure of the block indices).
// ---------------------------------------------------------------------------
__global__ void __launch_bounds__(256)
bin_kernel(const int* __restrict__ rows, const int* __restrict__ cols) {
    int e = blockIdx.x * blockDim.x + threadIdx.x;
    if (e >= NUM_EDGES) return;
    int dst4 = __ldg(&rows[e * 16]);
    int src4 = __ldg(&cols[e * 16]);
    int d = dst4 >> 2;
    int pos = atomicAdd(&g_count[d], 1);
    if (pos < CAP) g_bucket[(size_t)d * CAP + pos] = make_int2(e, src4);
}

// ---------------------------------------------------------------------------
// K3: gather. One warp per dst node; 4 lanes per edge, 8 edges per iteration.
// out[b, d*4+j] = bias[d*4+j] + sum_{e in adj(d)} sum_i v_e[i][j]*xt[src_e*4+i][b]
// No atomics: each warp owns its dst exclusively.
// ---------------------------------------------------------------------------
__global__ void __launch_bounds__(256)
gather_kernel(const float4* __restrict__ w_mean4,
              const float4* __restrict__ w_lv4,
              const float4* __restrict__ eps_w4,
              const float* __restrict__ b_mean,
              const float* __restrict__ b_log_var,
              const float* __restrict__ eps_b,
              float* __restrict__ out) {
    const unsigned FULL = 0xffffffffu;
    int lane = threadIdx.x & 31;
    int d = blockIdx.x * 8 + (threadIdx.x >> 5);
    if (d >= GS2) return;

    int n = g_count[d];
    if (n > CAP) n = CAP;
    const int2* bkt = g_bucket + (size_t)d * CAP;

    const int t = lane & 3;      // role within edge group: batches 2t, 2t+1 / v-row i=t
    const int g = lane >> 2;     // edge slot 0..7
    const int gbase = lane & ~3; // first lane of this 4-lane group

    // acc[j*2 + bb]: j = 0..3, bb in {0,1} -> batches 2t+bb
    float acc[8];
#pragma unroll
    for (int k = 0; k < 8; k++) acc[k] = 0.0f;

    for (int it = 0; it * 8 < n; it++) {
        int slot = g + it * 8;
        bool active = slot < n;
        int slot_c = active ? slot : 0;

        int2 es = __ldg(&bkt[slot_c]);
        int eid = es.x;
        int src4 = es.y;

        // v row i = t (float4 across j)
        float4 m  = __ldg(&w_mean4[eid * 4 + t]);
        float4 lv = __ldg(&w_lv4[eid * 4 + t]);
        float4 ep = __ldg(&eps_w4[eid * 4 + t]);
        float4 vo;
        vo.x = fmaf(ep.x, __expf(lv.x), m.x);
        vo.y = fmaf(ep.y, __expf(lv.y), m.y);
        vo.z = fmaf(ep.z, __expf(lv.z), m.z);
        vo.w = fmaf(ep.w, __expf(lv.w), m.w);
        if (!active) { vo.x = vo.y = vo.z = vo.w = 0.0f; }

        // x for batches 2t, 2t+1, rows i = 0..3 (from the 128B block at src4*32B)
        const float* xb = g_xt + (size_t)src4 * 8 + 2 * t;
        float2 xv[4];
#pragma unroll
        for (int i = 0; i < 4; i++)
            xv[i] = *reinterpret_cast<const float2*>(xb + i * 8);

        // fetch v rows i=0..3 from group lanes and accumulate
#pragma unroll
        for (int i = 0; i < 4; i++) {
            float vix = __shfl_sync(FULL, vo.x, gbase + i);
            float viy = __shfl_sync(FULL, vo.y, gbase + i);
            float viz = __shfl_sync(FULL, vo.z, gbase + i);
            float viw = __shfl_sync(FULL, vo.w, gbase + i);
            acc[0] = fmaf(vix, xv[i].x, acc[0]);
            acc[1] = fmaf(vix, xv[i].y, acc[1]);
            acc[2] = fmaf(viy, xv[i].x, acc[2]);
            acc[3] = fmaf(viy, xv[i].y, acc[3]);
            acc[4] = fmaf(viz, xv[i].x, acc[4]);
            acc[5] = fmaf(viz, xv[i].y, acc[5]);
            acc[6] = fmaf(viw, xv[i].x, acc[6]);
            acc[7] = fmaf(viw, xv[i].y, acc[7]);
        }
    }

    // reduce the 8 edge slots (lanes differing in bits 2..4)
#pragma unroll
    for (int off = 4; off <= 16; off <<= 1) {
#pragma unroll
        for (int k = 0; k < 8; k++)
            acc[k] += __shfl_xor_sync(FULL, acc[k], off);
    }

    // bias: lane computes bias[d*4 + t], broadcast within the warp
    int d4 = d * 4;
    float bias_own = fmaf(__ldg(&eps_b[d4 + t]), __expf(__ldg(&b_log_var[d4 + t])),
                          __ldg(&b_mean[d4 + t]));
    float bj0 = __shfl_sync(FULL, bias_own, 0);
    float bj1 = __shfl_sync(FULL, bias_own, 1);
    float bj2 = __shfl_sync(FULL, bias_own, 2);
    float bj3 = __shfl_sync(FULL, bias_own, 3);

    if (g == 0) {
        float4 o0, o1;
        o0.x = acc[0] + bj0; o0.y = acc[2] + bj1; o0.z = acc[4] + bj2; o0.w = acc[6] + bj3;
        o1.x = acc[1] + bj0; o1.y = acc[3] + bj1; o1.z = acc[5] + bj2; o1.w = acc[7] + bj3;
        *reinterpret_cast<float4*>(out + (size_t)(2 * t) * SIZE2 + d4) = o0;
        *reinterpret_cast<float4*>(out + (size_t)(2 * t + 1) * SIZE2 + d4) = o1;
    }
}

extern "C" void kernel_launch(void* const* d_in, const int* in_sizes, int n_in,
                              void* d_out, int out_size) {
    const float* x      = (const float*)d_in[0];
    const float* w_mean = (const float*)d_in[1];
    const float* w_lv   = (const float*)d_in[2];
    const float* b_mean = (const float*)d_in[3];
    const float* b_lv   = (const float*)d_in[4];
    const float* eps_w  = (const float*)d_in[5];
    const float* eps_b  = (const float*)d_in[6];
    const int*   rows   = (const int*)d_in[7];
    const int*   cols   = (const int*)d_in[8];
    float* out = (float*)d_out;

    prep_kernel<<<(SIZE1 + 255) / 256, 256>>>(x, out, out_size);

    bin_kernel<<<(NUM_EDGES + 255) / 256, 256>>>(rows, cols);

    gather_kernel<<<(GS2 * 32 + 255) / 256, 256>>>(
        (const float4*)w_mean, (const float4*)w_lv, (const float4*)eps_w,
        b_mean, b_lv, eps_b, out);
}